// round 13
// baseline (speedup 1.0000x reference)
#include <cuda_runtime.h>
#include <cuda_bf16.h>
#include <math.h>
#include <stdint.h>

#define B     128
#define H     1024
#define Z     256
#define SRC   64
#define KMAX  48
#define BH    (B*H)
#define X0LD  2432          // [z(256) | k(1) | attn(1024) | pad(127) | h0(1024)]
#define H0OFF 1408
#define X1LD  2048          // [h0n | h1]
#define G4    4096
#define KS_GATE 4
#define KS_GEN  8
#define KS_OUT  16
#define NC0   76            // X0LD/32
#define NC1   64
#define NCG   32
#define NCO   64

// out layout: z[B,K,Z] | mu | sigma | h_f[2,B,H] | c_f[2,B,H]
#define OUT_MU 1572864
#define OUT_SG 3145728
#define OUT_H  4718592
#define OUT_C  4980736

#define TILEB 4096          // bf16 elements per 128x32 W block
#define BUFB  40960         // bytes per smem buffer set
#define DSMEM 81920

typedef __nv_bfloat16 bf;

// ---------------- device scratch ----------------
__device__ __align__(16) float g_x0[B*X0LD];
__device__ __align__(16) float g_x1[B*X1LD];
__device__ __align__(16) float g_xa[B*X1LD];        // [weighted | q]
__device__ __align__(16) float g_c[2*BH];
__device__ __align__(16) float g_part[16*B*G4];
__device__ __align__(16) bf g_w0h[G4*X0LD], g_w0l[G4*X0LD];
__device__ __align__(16) bf g_w1h[G4*X1LD], g_w1l[G4*X1LD];
__device__ __align__(16) bf g_wgh[1536*H], g_wgl[1536*H];
__device__ __align__(16) bf g_woh[H*2048], g_wol[H*2048];

__device__ __forceinline__ float sigm(float x){ return 1.f/(1.f+expf(-x)); }

__device__ __forceinline__ void mma16816(float* c, const uint32_t* a, const uint32_t* b){
    asm volatile("mma.sync.aligned.m16n8k16.row.col.f32.bf16.bf16.f32 "
        "{%0,%1,%2,%3}, {%4,%5,%6,%7}, {%8,%9}, {%0,%1,%2,%3};"
        : "+f"(c[0]),"+f"(c[1]),"+f"(c[2]),"+f"(c[3])
        : "r"(a[0]),"r"(a[1]),"r"(a[2]),"r"(a[3]), "r"(b[0]),"r"(b[1]));
}
__device__ __forceinline__ void ldsm4(uint32_t* r, uint32_t addr){
    asm volatile("ldmatrix.sync.aligned.m8n8.x4.shared.b16 {%0,%1,%2,%3}, [%4];"
        : "=r"(r[0]),"=r"(r[1]),"=r"(r[2]),"=r"(r[3]) : "r"(addr));
}
__device__ __forceinline__ uint32_t smem_u32(const void* p){
    return (uint32_t)__cvta_generic_to_shared(p);
}

// ---------------- bf16x3 split-K GEMM via mma.sync + ldmatrix ----------------
// 128x128 tile, double-buffered smem, one sync per 32-k chunk.
__global__ __launch_bounds__(256) void tgemm(
    const float* __restrict__ A, int lda,
    const bf* __restrict__ Whi, const bf* __restrict__ Wlo,
    int NCg, int KPS)
{
    extern __shared__ __align__(16) char dyn[];

    const int t = threadIdx.x;
    const int w = t >> 5, lane = t & 31;
    const int g = lane >> 2, tig = lane & 3;
    const int ntile = blockIdx.x, z = blockIdx.y;
    const int n0 = ntile << 7;
    const int mrow = (w & 1) << 6;
    const int ncol = (w >> 1) << 5;
    const int lrow = t >> 1;
    const int lofs = (t & 1) << 4;

    // ldmatrix per-thread address components (bytes within a buffer)
    const uint32_t smem0 = smem_u32(dyn);
    const uint32_t aoff = (uint32_t)(mrow + (lane & 15)) * 80u + (uint32_t)((lane >> 4) << 3) * 2u;
    const uint32_t boff = (uint32_t)(ncol + lane) * 80u;

    const float* aptr = A + (size_t)lrow * lda + lofs + (size_t)(z * KPS) * 32;
    const bf* whp = Whi + ((size_t)(ntile * NCg + z * KPS) * 128 + lrow) * 32 + lofs;
    const bf* wlp = Wlo + ((size_t)(ntile * NCg + z * KPS) * 128 + lrow) * 32 + lofs;

    float acc[4][4][4];
#pragma unroll
    for (int i=0;i<4;i++)
#pragma unroll
        for (int j=0;j<4;j++)
#pragma unroll
            for (int q2=0;q2<4;q2++) acc[i][j][q2]=0.f;

    float4 fa0, fa1, fa2, fa3;
    uint4 wh0, wh1, wl0, wl1;

#define SAH(bu) ((bf(*)[40])(dyn + (bu)*BUFB))
#define SAL(bu) ((bf(*)[40])(dyn + (bu)*BUFB + 10240))
#define SWH(bu) ((bf(*)[40])(dyn + (bu)*BUFB + 20480))
#define SWL(bu) ((bf(*)[40])(dyn + (bu)*BUFB + 30720))

#define LOAD_REGS(ci) do { \
        const float* ap = aptr + (ci)*32; \
        fa0 = *(const float4*)(ap);    fa1 = *(const float4*)(ap+4); \
        fa2 = *(const float4*)(ap+8);  fa3 = *(const float4*)(ap+12); \
        wh0 = *(const uint4*)(whp + (size_t)(ci)*TILEB); \
        wh1 = *(const uint4*)(whp + (size_t)(ci)*TILEB + 8); \
        wl0 = *(const uint4*)(wlp + (size_t)(ci)*TILEB); \
        wl1 = *(const uint4*)(wlp + (size_t)(ci)*TILEB + 8); \
    } while(0)

#define STORE_SMEM(bu) do { \
        float fv[16] = {fa0.x,fa0.y,fa0.z,fa0.w, fa1.x,fa1.y,fa1.z,fa1.w, \
                        fa2.x,fa2.y,fa2.z,fa2.w, fa3.x,fa3.y,fa3.z,fa3.w}; \
        bf hv[16], lv[16]; \
        _Pragma("unroll") \
        for (int j=0;j<16;j++){ \
            hv[j] = __float2bfloat16(fv[j]); \
            lv[j] = __float2bfloat16(fv[j] - __bfloat162float(hv[j])); \
        } \
        *(uint4*)&SAH(bu)[lrow][lofs]   = *(uint4*)&hv[0]; \
        *(uint4*)&SAH(bu)[lrow][lofs+8] = *(uint4*)&hv[8]; \
        *(uint4*)&SAL(bu)[lrow][lofs]   = *(uint4*)&lv[0]; \
        *(uint4*)&SAL(bu)[lrow][lofs+8] = *(uint4*)&lv[8]; \
        *(uint4*)&SWH(bu)[lrow][lofs]   = wh0; \
        *(uint4*)&SWH(bu)[lrow][lofs+8] = wh1; \
        *(uint4*)&SWL(bu)[lrow][lofs]   = wl0; \
        *(uint4*)&SWL(bu)[lrow][lofs+8] = wl1; \
    } while(0)

    LOAD_REGS(0);
    STORE_SMEM(0);
    if (1 < KPS) LOAD_REGS(1);
    __syncthreads();

    for (int ci = 0; ci < KPS; ci++) {
        const int cur = ci & 1;
        if (ci + 1 < KPS) {
            STORE_SMEM(cur ^ 1);
            if (ci + 2 < KPS) LOAD_REGS(ci + 2);
        }
        const uint32_t bufb = smem0 + (uint32_t)cur * BUFB;
        const uint32_t aAh = bufb + aoff;
        const uint32_t aAl = aAh + 10240u;
        const uint32_t bWh = bufb + 20480u + boff;
        const uint32_t bWl = bWh + 10240u;
#pragma unroll
        for (int k16 = 0; k16 < 32; k16 += 16) {
            uint32_t Ah[4][4], Al[4][4], B0h[4], B1h[4], B0l[4], B1l[4];
#pragma unroll
            for (int mt=0; mt<4; mt++){
                ldsm4(Ah[mt], aAh + (uint32_t)(mt*16*80) + (uint32_t)(k16*2));
                ldsm4(Al[mt], aAl + (uint32_t)(mt*16*80) + (uint32_t)(k16*2));
            }
            ldsm4(B0h, bWh + (uint32_t)(k16*2));
            ldsm4(B1h, bWh + (uint32_t)(k16*2) + 16u);
            ldsm4(B0l, bWl + (uint32_t)(k16*2));
            ldsm4(B1l, bWl + (uint32_t)(k16*2) + 16u);
#pragma unroll
            for (int mt=0;mt<4;mt++)
#pragma unroll
                for (int nt=0;nt<4;nt++){
                    uint32_t bh2[2] = {B0h[nt], B1h[nt]};
                    uint32_t bl2[2] = {B0l[nt], B1l[nt]};
                    mma16816(acc[mt][nt], Ah[mt], bh2);
                    mma16816(acc[mt][nt], Ah[mt], bl2);
                    mma16816(acc[mt][nt], Al[mt], bh2);
                }
        }
        __syncthreads();
    }

#pragma unroll
    for (int mt=0; mt<4; mt++){
        int r0 = mrow + mt*16 + g;
#pragma unroll
        for (int nt=0; nt<4; nt++){
            int col = n0 + ncol + nt*8 + tig*2;
            float* p0 = g_part + ((size_t)(z*128 + r0))*4096 + col;
            float* p1 = g_part + ((size_t)(z*128 + r0 + 8))*4096 + col;
            *(float2*)p0 = make_float2(acc[mt][nt][0], acc[mt][nt][1]);
            *(float2*)p1 = make_float2(acc[mt][nt][2], acc[mt][nt][3]);
        }
    }
}

// ---------------- fused epilogues (proven) ----------------
__global__ void lstm_red(float* __restrict__ hst, int ldh, float* __restrict__ cst,
                         float* __restrict__ hout, int ldo,
                         const float* __restrict__ bi, const float* __restrict__ bh,
                         const int* __restrict__ kin, int step)
{
    int i = blockIdx.x*256 + threadIdx.x;            // BH
    int b = i >> 10, hh = i & 1023;
    float g[4];
#pragma unroll
    for (int gi=0; gi<4; gi++) {
        int col = (gi<<10) + hh;
        float s = bi[col] + bh[col];
#pragma unroll
        for (int zz=0; zz<KS_GATE; zz++)
            s += g_part[((size_t)(zz*128+b))*4096 + col];
        g[gi] = s;
    }
    float* hp = hst + (size_t)b*ldh + hh;
    float ho = *hp, co = cst[i];
    float cn = sigm(g[1])*co + sigm(g[0])*tanhf(g[2]);
    float hn = sigm(g[3])*tanhf(cn);
    hout[(size_t)b*ldo + hh] = hn;
    bool frozen = step >= kin[b];
    *hp    = frozen ? ho : hn;
    cst[i] = frozen ? co : cn;
}

__global__ void attn_core(const float* __restrict__ ctx, float* __restrict__ out,
                          const float* __restrict__ eps,
                          const float* __restrict__ mub, const float* __restrict__ sgb,
                          const int* __restrict__ kin, int step)
{
    __shared__ float sq[H];
    __shared__ float sal[SRC];
    int b = blockIdx.x, t = threadIdx.x;

    if (step >= 0) {                                 // fused zstep
        int zi = t;
        float m = mub[zi], s = sgb[zi];
#pragma unroll
        for (int zz=0; zz<KS_GEN; zz++) {
            const float* p = g_part + ((size_t)(zz*128+b))*4096;
            m += p[zi];
            s += p[256+zi];
        }
        float zval = m + expf(s) * eps[((size_t)step*B + b)*Z + zi];
        g_x0[(size_t)b*X0LD + zi] = zval;
        bool valid = step < kin[b];
        size_t o = ((size_t)b*KMAX + step)*Z + zi;
        out[o]          = valid ? zval : 0.f;
        out[OUT_MU + o] = valid ? m : 0.f;
        out[OUT_SG + o] = valid ? s : 0.f;
    }

    for (int i=t; i<H; i+=256) {                     // qw reduce (cols 512..1535)
        float s = 0.f;
#pragma unroll
        for (int zz=0; zz<KS_GEN; zz++)
            s += g_part[((size_t)(zz*128+b))*4096 + 512 + i];
        sq[i] = s;
    }
    __syncthreads();
    int warp = t>>5, lane = t&31;
#pragma unroll
    for (int s8=0; s8<8; s8++) {
        int s = warp*8 + s8;
        const float* cr = ctx + ((size_t)b*SRC + s)*H;
        float a = 0.f;
        for (int k2=lane; k2<H; k2+=32) a += cr[k2]*sq[k2];
#pragma unroll
        for (int o=16;o>0;o>>=1) a += __shfl_xor_sync(0xffffffffu, a, o);
        if (lane==0) sal[s] = a;
    }
    __syncthreads();
    if (warp==0) {
        float v0 = sal[lane], v1 = sal[lane+32];
        float mx = fmaxf(v0,v1);
#pragma unroll
        for (int o=16;o>0;o>>=1) mx = fmaxf(mx, __shfl_xor_sync(0xffffffffu,mx,o));
        float e0=expf(v0-mx), e1=expf(v1-mx);
        float sm=e0+e1;
#pragma unroll
        for (int o=16;o>0;o>>=1) sm += __shfl_xor_sync(0xffffffffu,sm,o);
        float inv=1.f/sm;
        sal[lane]=e0*inv; sal[lane+32]=e1*inv;
    }
    __syncthreads();
    for (int hh=t; hh<H; hh+=256) {
        float a=0.f;
#pragma unroll 8
        for (int s=0;s<SRC;s++) a += sal[s]*ctx[((size_t)b*SRC+s)*H + hh];
        g_xa[(size_t)b*X1LD + hh] = a;
    }
}

__global__ void attnout_red()
{
    int i = blockIdx.x*256 + threadIdx.x;            // BH
    int b = i>>10, hh = i&1023;
    float s = 0.f;
#pragma unroll
    for (int zz=0; zz<KS_OUT; zz++)
        s += g_part[((size_t)(zz*128+b))*4096 + hh];
    g_x0[(size_t)b*X0LD + 257 + hh] = tanhf(s);
}

// ---------------- weight prep: fp32 -> bf16 hi/lo blocked (128x32) -----------
__device__ __forceinline__ void put_tile(bf* hi, bf* lo, int NCg, int n, int k, float v){
    int ntile = n >> 7, nin = n & 127, chunk = k >> 5, kin = k & 31;
    size_t d = ((size_t)(ntile * NCg + chunk) * 128 + nin) * 32 + kin;
    bf h = __float2bfloat16(v);
    hi[d] = h;
    lo[d] = __float2bfloat16(v - __bfloat162float(h));
}
__global__ void prep0(const float* __restrict__ Wih, const float* __restrict__ Whh){
    int i = blockIdx.x*256 + threadIdx.x;
    int n = i / X0LD, k = i - n*X0LD;
    float v;
    if (k < 1281)       v = Wih[(size_t)n*1281 + k];
    else if (k < H0OFF) v = 0.f;
    else                v = Whh[(size_t)n*1024 + (k-H0OFF)];
    put_tile(g_w0h, g_w0l, NC0, n, k, v);
}
__global__ void prep1(const float* __restrict__ Wih, const float* __restrict__ Whh){
    int i = blockIdx.x*256 + threadIdx.x;
    int n = i >> 11, k = i & 2047;
    float v = (k < 1024) ? Wih[(size_t)n*1024 + k] : Whh[(size_t)n*1024 + (k-1024)];
    put_tile(g_w1h, g_w1l, NC1, n, k, v);
}
__global__ void prepg(const float* __restrict__ muW, const float* __restrict__ sgW,
                      const float* __restrict__ aWin){
    int i = blockIdx.x*256 + threadIdx.x;
    int n = i >> 10, k = i & 1023;
    float v;
    if (n < 256)      v = muW[(size_t)n*1024 + k];
    else if (n < 512) v = sgW[(size_t)(n-256)*1024 + k];
    else              v = aWin[(size_t)(n-512)*1024 + k];
    put_tile(g_wgh, g_wgl, NCG, n, k, v);
}
__global__ void prepo(const float* __restrict__ aWout){
    int i = blockIdx.x*256 + threadIdx.x;
    int n = i >> 11, k = i & 2047;
    put_tile(g_woh, g_wol, NCO, n, k, aWout[(size_t)n*2048 + k]);
}

// ---------------- init / final ----------------
__global__ void init_a(const float* __restrict__ z0, const int* __restrict__ kin,
                       const float* __restrict__ h0){
    int i = blockIdx.x*256 + threadIdx.x;
    int b = i / X0LD, c = i - b*X0LD;
    float v = 0.f;
    if (c < 256)         v = z0[(b<<8) + c];
    else if (c == 256)   v = (float)kin[b];
    else if (c >= H0OFF) v = h0[(b<<10) + (c-H0OFF)];
    g_x0[i] = v;
}
__global__ void init_b(const float* __restrict__ h0, const float* __restrict__ c0){
    int i = blockIdx.x*256 + threadIdx.x;
    int b = i >> 11, c = i & 2047;
    g_x1[i] = (c < 1024) ? 0.f : h0[BH + (b<<10) + (c-1024)];
    g_xa[i] = (c < 1024) ? 0.f : c0[BH + (b<<10) + (c-1024)];
    g_c[i]  = c0[i];
}
__global__ void final_copy(float* __restrict__ out){
    int i = blockIdx.x*256 + threadIdx.x;
    int b = i>>10, hh = i&1023;
    out[OUT_H + i]      = g_x0[(size_t)b*X0LD + H0OFF + hh];
    out[OUT_H + BH + i] = g_x1[(size_t)b*X1LD + 1024 + hh];
    out[OUT_C + i]      = g_c[i];
    out[OUT_C + BH + i] = g_c[BH + i];
}

// ---------------- orchestration ----------------
extern "C" void kernel_launch(void* const* d_in, const int* in_sizes, int n_in,
                              void* d_out, int out_size) {
    const float* h0    = (const float*)d_in[0];
    const float* c0    = (const float*)d_in[1];
    const float* ctx   = (const float*)d_in[2];
    const float* z0    = (const float*)d_in[3];
    const int*   kin   = (const int*)  d_in[4];
    const float* eps   = (const float*)d_in[5];
    const float* W_ih0 = (const float*)d_in[6];
    const float* W_hh0 = (const float*)d_in[7];
    const float* b_ih0 = (const float*)d_in[8];
    const float* b_hh0 = (const float*)d_in[9];
    const float* W_ih1 = (const float*)d_in[10];
    const float* W_hh1 = (const float*)d_in[11];
    const float* b_ih1 = (const float*)d_in[12];
    const float* b_hh1 = (const float*)d_in[13];
    const float* aWin  = (const float*)d_in[14];
    const float* aWout = (const float*)d_in[15];
    const float* mu_W  = (const float*)d_in[16];
    const float* mu_b  = (const float*)d_in[17];
    const float* sg_W  = (const float*)d_in[18];
    const float* sg_b  = (const float*)d_in[19];
    float* out = (float*)d_out;

    static int s_attr_set = 0;
    if (!s_attr_set) {
        cudaFuncSetAttribute(tgemm, cudaFuncAttributeMaxDynamicSharedMemorySize, DSMEM);
        s_attr_set = 1;
    }

    float *p_x0, *p_x1, *p_xa, *p_c;
    bf *w0h, *w0l, *w1h, *w1l, *wgh, *wgl, *woh, *wol;
    cudaGetSymbolAddress((void**)&p_x0, g_x0);
    cudaGetSymbolAddress((void**)&p_x1, g_x1);
    cudaGetSymbolAddress((void**)&p_xa, g_xa);
    cudaGetSymbolAddress((void**)&p_c,  g_c);
    cudaGetSymbolAddress((void**)&w0h, g_w0h);
    cudaGetSymbolAddress((void**)&w0l, g_w0l);
    cudaGetSymbolAddress((void**)&w1h, g_w1h);
    cudaGetSymbolAddress((void**)&w1l, g_w1l);
    cudaGetSymbolAddress((void**)&wgh, g_wgh);
    cudaGetSymbolAddress((void**)&wgl, g_wgl);
    cudaGetSymbolAddress((void**)&woh, g_woh);
    cudaGetSymbolAddress((void**)&wol, g_wol);

    prep0<<<(G4*X0LD)/256, 256>>>(W_ih0, W_hh0);
    prep1<<<(G4*X1LD)/256, 256>>>(W_ih1, W_hh1);
    prepg<<<(1536*H)/256, 256>>>(mu_W, sg_W, aWin);
    prepo<<<(H*2048)/256, 256>>>(aWout);
    init_a<<<(B*X0LD)/256, 256>>>(z0, kin, h0);
    init_b<<<(B*X1LD)/256, 256>>>(h0, c0);

    // attn0: q = c0[-1] (step=-1 skips fused zstep)
    tgemm<<<dim3(12, KS_GEN), 256, DSMEM>>>(c0 + BH, H, wgh, wgl, NCG, NCG/KS_GEN);
    attn_core<<<B, 256>>>(ctx, out, eps, mu_b, sg_b, kin, -1);
    tgemm<<<dim3(8, KS_OUT), 256, DSMEM>>>(p_xa, X1LD, woh, wol, NCO, NCO/KS_OUT);
    attnout_red<<<BH/256, 256>>>();

    for (int step = 0; step < KMAX; step++) {
        tgemm<<<dim3(32, KS_GATE), 256, DSMEM>>>(p_x0, X0LD, w0h, w0l, NC0, NC0/KS_GATE);
        lstm_red<<<BH/256, 256>>>(p_x0 + H0OFF, X0LD, p_c, p_x1, X1LD, b_ih0, b_hh0, kin, step);
        tgemm<<<dim3(32, KS_GATE), 256, DSMEM>>>(p_x1, X1LD, w1h, w1l, NC1, NC1/KS_GATE);
        lstm_red<<<BH/256, 256>>>(p_x1 + 1024, X1LD, p_c + BH, p_xa + 1024, X1LD, b_ih1, b_hh1, kin, step);
        tgemm<<<dim3(12, KS_GEN), 256, DSMEM>>>(p_xa + 1024, X1LD, wgh, wgl, NCG, NCG/KS_GEN);
        attn_core<<<B, 256>>>(ctx, out, eps, mu_b, sg_b, kin, step);
        tgemm<<<dim3(8, KS_OUT), 256, DSMEM>>>(p_xa, X1LD, woh, wol, NCO, NCO/KS_OUT);
        attnout_red<<<BH/256, 256>>>();
    }

    final_copy<<<BH/256, 256>>>(out);
    (void)in_sizes; (void)n_in; (void)out_size;
}

// round 14
// speedup vs baseline: 1.2553x; 1.2553x over previous
#include <cuda_runtime.h>
#include <cuda_fp16.h>
#include <math.h>
#include <stdint.h>

#define B     128
#define H     1024
#define Z     256
#define SRC   64
#define KMAX  48
#define BH    (B*H)
#define X0LD  2432          // [z(256) | k(1) | attn(1024) | pad(127) | h0(1024)]
#define H0OFF 1408
#define X1LD  2048          // [h0n | h1]
#define G4    4096
#define KS_GATE 4
#define KS_GEN  8
#define KS_OUT  16
#define NC0   76            // X0LD/32
#define NC1   64
#define NCG   32
#define NCO   64

// out layout: z[B,K,Z] | mu | sigma | h_f[2,B,H] | c_f[2,B,H]
#define OUT_MU 1572864
#define OUT_SG 3145728
#define OUT_H  4718592
#define OUT_C  4980736

#define TILEB 4096          // fp16 elements per 128x32 W block
#define BUFB  30720         // bytes per smem buffer set (Ah,Al,W)
#define DSMEM 61440

typedef __half hf;

// ---------------- device scratch ----------------
__device__ __align__(16) float g_x0[B*X0LD];
__device__ __align__(16) float g_x1[B*X1LD];
__device__ __align__(16) float g_xa[B*X1LD];        // [weighted | q]
__device__ __align__(16) float g_c[2*BH];
__device__ __align__(16) float g_part[16*B*G4];
__device__ __align__(16) hf g_w0[G4*X0LD];
__device__ __align__(16) hf g_w1[G4*X1LD];
__device__ __align__(16) hf g_wg[1536*H];
__device__ __align__(16) hf g_wo[H*2048];

__device__ __forceinline__ float sigm(float x){ return 1.f/(1.f+expf(-x)); }

__device__ __forceinline__ void mma16816(float* c, const uint32_t* a, const uint32_t* b){
    asm volatile("mma.sync.aligned.m16n8k16.row.col.f32.f16.f16.f32 "
        "{%0,%1,%2,%3}, {%4,%5,%6,%7}, {%8,%9}, {%0,%1,%2,%3};"
        : "+f"(c[0]),"+f"(c[1]),"+f"(c[2]),"+f"(c[3])
        : "r"(a[0]),"r"(a[1]),"r"(a[2]),"r"(a[3]), "r"(b[0]),"r"(b[1]));
}
__device__ __forceinline__ void ldsm4(uint32_t* r, uint32_t addr){
    asm volatile("ldmatrix.sync.aligned.m8n8.x4.shared.b16 {%0,%1,%2,%3}, [%4];"
        : "=r"(r[0]),"=r"(r[1]),"=r"(r[2]),"=r"(r[3]) : "r"(addr));
}
__device__ __forceinline__ uint32_t smem_u32(const void* p){
    return (uint32_t)__cvta_generic_to_shared(p);
}

// ---------------- fp16 2-pass split-K GEMM (A hi/lo exact, W single) ---------
// 128x128 tile, double-buffered smem, one sync per 32-k chunk.
__global__ __launch_bounds__(256) void tgemm(
    const float* __restrict__ A, int lda,
    const hf* __restrict__ W,
    int NCg, int KPS)
{
    extern __shared__ __align__(16) char dyn[];

    const int t = threadIdx.x;
    const int w = t >> 5, lane = t & 31;
    const int g = lane >> 2, tig = lane & 3;
    const int ntile = blockIdx.x, z = blockIdx.y;
    const int n0 = ntile << 7;
    const int mrow = (w & 1) << 6;
    const int ncol = (w >> 1) << 5;
    const int lrow = t >> 1;
    const int lofs = (t & 1) << 4;

    const uint32_t smem0 = smem_u32(dyn);
    const uint32_t aoff = (uint32_t)(mrow + (lane & 15)) * 80u + (uint32_t)((lane >> 4) << 3) * 2u;
    const uint32_t boff = (uint32_t)(ncol + lane) * 80u;

    const float* aptr = A + (size_t)lrow * lda + lofs + (size_t)(z * KPS) * 32;
    const hf* wp = W + ((size_t)(ntile * NCg + z * KPS) * 128 + lrow) * 32 + lofs;

    float acc[4][4][4];
#pragma unroll
    for (int i=0;i<4;i++)
#pragma unroll
        for (int j=0;j<4;j++)
#pragma unroll
            for (int q2=0;q2<4;q2++) acc[i][j][q2]=0.f;

    float4 fa0, fa1, fa2, fa3;
    uint4 wr0, wr1;

#define SAH(bu) ((hf(*)[40])(dyn + (bu)*BUFB))
#define SAL(bu) ((hf(*)[40])(dyn + (bu)*BUFB + 10240))
#define SWW(bu) ((hf(*)[40])(dyn + (bu)*BUFB + 20480))

#define LOAD_REGS(ci) do { \
        const float* ap = aptr + (ci)*32; \
        fa0 = *(const float4*)(ap);    fa1 = *(const float4*)(ap+4); \
        fa2 = *(const float4*)(ap+8);  fa3 = *(const float4*)(ap+12); \
        wr0 = *(const uint4*)(wp + (size_t)(ci)*TILEB); \
        wr1 = *(const uint4*)(wp + (size_t)(ci)*TILEB + 8); \
    } while(0)

#define STORE_SMEM(bu) do { \
        float fv[16] = {fa0.x,fa0.y,fa0.z,fa0.w, fa1.x,fa1.y,fa1.z,fa1.w, \
                        fa2.x,fa2.y,fa2.z,fa2.w, fa3.x,fa3.y,fa3.z,fa3.w}; \
        hf hv[16], lv[16]; \
        _Pragma("unroll") \
        for (int j=0;j<16;j++){ \
            hv[j] = __float2half(fv[j]); \
            lv[j] = __float2half(fv[j] - __half2float(hv[j])); \
        } \
        *(uint4*)&SAH(bu)[lrow][lofs]   = *(uint4*)&hv[0]; \
        *(uint4*)&SAH(bu)[lrow][lofs+8] = *(uint4*)&hv[8]; \
        *(uint4*)&SAL(bu)[lrow][lofs]   = *(uint4*)&lv[0]; \
        *(uint4*)&SAL(bu)[lrow][lofs+8] = *(uint4*)&lv[8]; \
        *(uint4*)&SWW(bu)[lrow][lofs]   = wr0; \
        *(uint4*)&SWW(bu)[lrow][lofs+8] = wr1; \
    } while(0)

    LOAD_REGS(0);
    STORE_SMEM(0);
    if (1 < KPS) LOAD_REGS(1);
    __syncthreads();

    for (int ci = 0; ci < KPS; ci++) {
        const int cur = ci & 1;
        if (ci + 1 < KPS) {
            STORE_SMEM(cur ^ 1);
            if (ci + 2 < KPS) LOAD_REGS(ci + 2);
        }
        const uint32_t bufb = smem0 + (uint32_t)cur * BUFB;
        const uint32_t aAh = bufb + aoff;
        const uint32_t aAl = aAh + 10240u;
        const uint32_t bW  = bufb + 20480u + boff;
#pragma unroll
        for (int k16 = 0; k16 < 32; k16 += 16) {
            uint32_t Ah[4][4], Al[4][4], B0[4], B1[4];
#pragma unroll
            for (int mt=0; mt<4; mt++){
                ldsm4(Ah[mt], aAh + (uint32_t)(mt*16*80) + (uint32_t)(k16*2));
                ldsm4(Al[mt], aAl + (uint32_t)(mt*16*80) + (uint32_t)(k16*2));
            }
            ldsm4(B0, bW + (uint32_t)(k16*2));
            ldsm4(B1, bW + (uint32_t)(k16*2) + 16u);
#pragma unroll
            for (int mt=0;mt<4;mt++)
#pragma unroll
                for (int nt=0;nt<4;nt++){
                    uint32_t b2[2] = {B0[nt], B1[nt]};
                    mma16816(acc[mt][nt], Ah[mt], b2);
                    mma16816(acc[mt][nt], Al[mt], b2);
                }
        }
        __syncthreads();
    }

#pragma unroll
    for (int mt=0; mt<4; mt++){
        int r0 = mrow + mt*16 + g;
#pragma unroll
        for (int nt=0; nt<4; nt++){
            int col = n0 + ncol + nt*8 + tig*2;
            float* p0 = g_part + ((size_t)(z*128 + r0))*4096 + col;
            float* p1 = g_part + ((size_t)(z*128 + r0 + 8))*4096 + col;
            *(float2*)p0 = make_float2(acc[mt][nt][0], acc[mt][nt][1]);
            *(float2*)p1 = make_float2(acc[mt][nt][2], acc[mt][nt][3]);
        }
    }
}

// ---------------- fused epilogues (proven) ----------------
__global__ void lstm_red(float* __restrict__ hst, int ldh, float* __restrict__ cst,
                         float* __restrict__ hout, int ldo,
                         const float* __restrict__ bi, const float* __restrict__ bh,
                         const int* __restrict__ kin, int step)
{
    int i = blockIdx.x*256 + threadIdx.x;            // BH
    int b = i >> 10, hh = i & 1023;
    float g[4];
#pragma unroll
    for (int gi=0; gi<4; gi++) {
        int col = (gi<<10) + hh;
        float s = bi[col] + bh[col];
#pragma unroll
        for (int zz=0; zz<KS_GATE; zz++)
            s += g_part[((size_t)(zz*128+b))*4096 + col];
        g[gi] = s;
    }
    float* hp = hst + (size_t)b*ldh + hh;
    float ho = *hp, co = cst[i];
    float cn = sigm(g[1])*co + sigm(g[0])*tanhf(g[2]);
    float hn = sigm(g[3])*tanhf(cn);
    hout[(size_t)b*ldo + hh] = hn;
    bool frozen = step >= kin[b];
    *hp    = frozen ? ho : hn;
    cst[i] = frozen ? co : cn;
}

__global__ void attn_core(const float* __restrict__ ctx, float* __restrict__ out,
                          const float* __restrict__ eps,
                          const float* __restrict__ mub, const float* __restrict__ sgb,
                          const int* __restrict__ kin, int step)
{
    __shared__ float sq[H];
    __shared__ float sal[SRC];
    int b = blockIdx.x, t = threadIdx.x;

    if (step >= 0) {                                 // fused zstep
        int zi = t;
        float m = mub[zi], s = sgb[zi];
#pragma unroll
        for (int zz=0; zz<KS_GEN; zz++) {
            const float* p = g_part + ((size_t)(zz*128+b))*4096;
            m += p[zi];
            s += p[256+zi];
        }
        float zval = m + expf(s) * eps[((size_t)step*B + b)*Z + zi];
        g_x0[(size_t)b*X0LD + zi] = zval;
        bool valid = step < kin[b];
        size_t o = ((size_t)b*KMAX + step)*Z + zi;
        out[o]          = valid ? zval : 0.f;
        out[OUT_MU + o] = valid ? m : 0.f;
        out[OUT_SG + o] = valid ? s : 0.f;
    }

    for (int i=t; i<H; i+=256) {                     // qw reduce (cols 512..1535)
        float s = 0.f;
#pragma unroll
        for (int zz=0; zz<KS_GEN; zz++)
            s += g_part[((size_t)(zz*128+b))*4096 + 512 + i];
        sq[i] = s;
    }
    __syncthreads();
    int warp = t>>5, lane = t&31;
#pragma unroll
    for (int s8=0; s8<8; s8++) {
        int s = warp*8 + s8;
        const float* cr = ctx + ((size_t)b*SRC + s)*H;
        float a = 0.f;
        for (int k2=lane; k2<H; k2+=32) a += cr[k2]*sq[k2];
#pragma unroll
        for (int o=16;o>0;o>>=1) a += __shfl_xor_sync(0xffffffffu, a, o);
        if (lane==0) sal[s] = a;
    }
    __syncthreads();
    if (warp==0) {
        float v0 = sal[lane], v1 = sal[lane+32];
        float mx = fmaxf(v0,v1);
#pragma unroll
        for (int o=16;o>0;o>>=1) mx = fmaxf(mx, __shfl_xor_sync(0xffffffffu,mx,o));
        float e0=expf(v0-mx), e1=expf(v1-mx);
        float sm=e0+e1;
#pragma unroll
        for (int o=16;o>0;o>>=1) sm += __shfl_xor_sync(0xffffffffu,sm,o);
        float inv=1.f/sm;
        sal[lane]=e0*inv; sal[lane+32]=e1*inv;
    }
    __syncthreads();
    for (int hh=t; hh<H; hh+=256) {
        float a=0.f;
#pragma unroll 8
        for (int s=0;s<SRC;s++) a += sal[s]*ctx[((size_t)b*SRC+s)*H + hh];
        g_xa[(size_t)b*X1LD + hh] = a;
    }
}

__global__ void attnout_red()
{
    int i = blockIdx.x*256 + threadIdx.x;            // BH
    int b = i>>10, hh = i&1023;
    float s = 0.f;
#pragma unroll
    for (int zz=0; zz<KS_OUT; zz++)
        s += g_part[((size_t)(zz*128+b))*4096 + hh];
    g_x0[(size_t)b*X0LD + 257 + hh] = tanhf(s);
}

// ---------------- weight prep: fp32 -> fp16 blocked (128x32) ----------------
__device__ __forceinline__ void put_tile(hf* dst, int NCg, int n, int k, float v){
    int ntile = n >> 7, nin = n & 127, chunk = k >> 5, kin = k & 31;
    size_t d = ((size_t)(ntile * NCg + chunk) * 128 + nin) * 32 + kin;
    dst[d] = __float2half(v);
}
__global__ void prep0(const float* __restrict__ Wih, const float* __restrict__ Whh){
    int i = blockIdx.x*256 + threadIdx.x;
    int n = i / X0LD, k = i - n*X0LD;
    float v;
    if (k < 1281)       v = Wih[(size_t)n*1281 + k];
    else if (k < H0OFF) v = 0.f;
    else                v = Whh[(size_t)n*1024 + (k-H0OFF)];
    put_tile(g_w0, NC0, n, k, v);
}
__global__ void prep1(const float* __restrict__ Wih, const float* __restrict__ Whh){
    int i = blockIdx.x*256 + threadIdx.x;
    int n = i >> 11, k = i & 2047;
    float v = (k < 1024) ? Wih[(size_t)n*1024 + k] : Whh[(size_t)n*1024 + (k-1024)];
    put_tile(g_w1, NC1, n, k, v);
}
__global__ void prepg(const float* __restrict__ muW, const float* __restrict__ sgW,
                      const float* __restrict__ aWin){
    int i = blockIdx.x*256 + threadIdx.x;
    int n = i >> 10, k = i & 1023;
    float v;
    if (n < 256)      v = muW[(size_t)n*1024 + k];
    else if (n < 512) v = sgW[(size_t)(n-256)*1024 + k];
    else              v = aWin[(size_t)(n-512)*1024 + k];
    put_tile(g_wg, NCG, n, k, v);
}
__global__ void prepo(const float* __restrict__ aWout){
    int i = blockIdx.x*256 + threadIdx.x;
    int n = i >> 11, k = i & 2047;
    put_tile(g_wo, NCO, n, k, aWout[(size_t)n*2048 + k]);
}

// ---------------- init / final ----------------
__global__ void init_a(const float* __restrict__ z0, const int* __restrict__ kin,
                       const float* __restrict__ h0){
    int i = blockIdx.x*256 + threadIdx.x;
    int b = i / X0LD, c = i - b*X0LD;
    float v = 0.f;
    if (c < 256)         v = z0[(b<<8) + c];
    else if (c == 256)   v = (float)kin[b];
    else if (c >= H0OFF) v = h0[(b<<10) + (c-H0OFF)];
    g_x0[i] = v;
}
__global__ void init_b(const float* __restrict__ h0, const float* __restrict__ c0){
    int i = blockIdx.x*256 + threadIdx.x;
    int b = i >> 11, c = i & 2047;
    g_x1[i] = (c < 1024) ? 0.f : h0[BH + (b<<10) + (c-1024)];
    g_xa[i] = (c < 1024) ? 0.f : c0[BH + (b<<10) + (c-1024)];
    g_c[i]  = c0[i];
}
__global__ void final_copy(float* __restrict__ out){
    int i = blockIdx.x*256 + threadIdx.x;
    int b = i>>10, hh = i&1023;
    out[OUT_H + i]      = g_x0[(size_t)b*X0LD + H0OFF + hh];
    out[OUT_H + BH + i] = g_x1[(size_t)b*X1LD + 1024 + hh];
    out[OUT_C + i]      = g_c[i];
    out[OUT_C + BH + i] = g_c[BH + i];
}

// ---------------- orchestration ----------------
extern "C" void kernel_launch(void* const* d_in, const int* in_sizes, int n_in,
                              void* d_out, int out_size) {
    const float* h0    = (const float*)d_in[0];
    const float* c0    = (const float*)d_in[1];
    const float* ctx   = (const float*)d_in[2];
    const float* z0    = (const float*)d_in[3];
    const int*   kin   = (const int*)  d_in[4];
    const float* eps   = (const float*)d_in[5];
    const float* W_ih0 = (const float*)d_in[6];
    const float* W_hh0 = (const float*)d_in[7];
    const float* b_ih0 = (const float*)d_in[8];
    const float* b_hh0 = (const float*)d_in[9];
    const float* W_ih1 = (const float*)d_in[10];
    const float* W_hh1 = (const float*)d_in[11];
    const float* b_ih1 = (const float*)d_in[12];
    const float* b_hh1 = (const float*)d_in[13];
    const float* aWin  = (const float*)d_in[14];
    const float* aWout = (const float*)d_in[15];
    const float* mu_W  = (const float*)d_in[16];
    const float* mu_b  = (const float*)d_in[17];
    const float* sg_W  = (const float*)d_in[18];
    const float* sg_b  = (const float*)d_in[19];
    float* out = (float*)d_out;

    static int s_attr_set = 0;
    if (!s_attr_set) {
        cudaFuncSetAttribute(tgemm, cudaFuncAttributeMaxDynamicSharedMemorySize, DSMEM);
        s_attr_set = 1;
    }

    float *p_x0, *p_x1, *p_xa, *p_c;
    hf *w0, *w1, *wg, *wo;
    cudaGetSymbolAddress((void**)&p_x0, g_x0);
    cudaGetSymbolAddress((void**)&p_x1, g_x1);
    cudaGetSymbolAddress((void**)&p_xa, g_xa);
    cudaGetSymbolAddress((void**)&p_c,  g_c);
    cudaGetSymbolAddress((void**)&w0, g_w0);
    cudaGetSymbolAddress((void**)&w1, g_w1);
    cudaGetSymbolAddress((void**)&wg, g_wg);
    cudaGetSymbolAddress((void**)&wo, g_wo);

    prep0<<<(G4*X0LD)/256, 256>>>(W_ih0, W_hh0);
    prep1<<<(G4*X1LD)/256, 256>>>(W_ih1, W_hh1);
    prepg<<<(1536*H)/256, 256>>>(mu_W, sg_W, aWin);
    prepo<<<(H*2048)/256, 256>>>(aWout);
    init_a<<<(B*X0LD)/256, 256>>>(z0, kin, h0);
    init_b<<<(B*X1LD)/256, 256>>>(h0, c0);

    // attn0: q = c0[-1] (step=-1 skips fused zstep)
    tgemm<<<dim3(12, KS_GEN), 256, DSMEM>>>(c0 + BH, H, wg, NCG, NCG/KS_GEN);
    attn_core<<<B, 256>>>(ctx, out, eps, mu_b, sg_b, kin, -1);
    tgemm<<<dim3(8, KS_OUT), 256, DSMEM>>>(p_xa, X1LD, wo, NCO, NCO/KS_OUT);
    attnout_red<<<BH/256, 256>>>();

    for (int step = 0; step < KMAX; step++) {
        tgemm<<<dim3(32, KS_GATE), 256, DSMEM>>>(p_x0, X0LD, w0, NC0, NC0/KS_GATE);
        lstm_red<<<BH/256, 256>>>(p_x0 + H0OFF, X0LD, p_c, p_x1, X1LD, b_ih0, b_hh0, kin, step);
        tgemm<<<dim3(32, KS_GATE), 256, DSMEM>>>(p_x1, X1LD, w1, NC1, NC1/KS_GATE);
        lstm_red<<<BH/256, 256>>>(p_x1 + 1024, X1LD, p_c + BH, p_xa + 1024, X1LD, b_ih1, b_hh1, kin, step);
        tgemm<<<dim3(12, KS_GEN), 256, DSMEM>>>(p_xa + 1024, X1LD, wg, NCG, NCG/KS_GEN);
        attn_core<<<B, 256>>>(ctx, out, eps, mu_b, sg_b, kin, step);
        tgemm<<<dim3(8, KS_OUT), 256, DSMEM>>>(p_xa, X1LD, wo, NCO, NCO/KS_OUT);
        attnout_red<<<BH/256, 256>>>();
    }

    final_copy<<<BH/256, 256>>>(out);
    (void)in_sizes; (void)n_in; (void)out_size;
}

// round 15
// speedup vs baseline: 1.3117x; 1.0449x over previous
#include <cuda_runtime.h>
#include <cuda_fp16.h>
#include <math.h>
#include <stdint.h>

#define B     128
#define H     1024
#define Z     256
#define SRC   64
#define KMAX  48
#define BH    (B*H)
#define X0LD  2432          // [z(256) | k(1) | attn(1024) | pad(127) | h0(1024)]
#define H0OFF 1408
#define X1LD  2048          // [h0n | h1]
#define G4    4096
#define KS_GATE 4
#define KS_GEN  8
#define KS_OUT  16
#define NC0   76            // X0LD/32
#define NC1   64
#define NCG   32
#define NCO   64

// out layout: z[B,K,Z] | mu | sigma | h_f[2,B,H] | c_f[2,B,H]
#define OUT_MU 1572864
#define OUT_SG 3145728
#define OUT_H  4718592
#define OUT_C  4980736

#define TILEB 4096          // fp16 elements per 128x32 W block
#define BUFB  30720         // bytes per smem buffer set (Ah,Al,W)
#define DSMEM 61440

typedef __half hf;

// ---------------- device scratch ----------------
__device__ __align__(16) float g_x0[B*X0LD];
__device__ __align__(16) float g_x1[B*X1LD];
__device__ __align__(16) float g_xa[B*X1LD];        // [weighted | q]
__device__ __align__(16) float g_c[2*BH];
__device__ __align__(16) float g_part[16*B*G4];
__device__ __align__(16) hf g_w0[G4*X0LD];
__device__ __align__(16) hf g_w1[G4*X1LD];
__device__ __align__(16) hf g_wg[1536*H];
__device__ __align__(16) hf g_wo[H*2048];

__device__ __forceinline__ float sigm(float x){ return 1.f/(1.f+expf(-x)); }
__device__ __forceinline__ void grid_wait(){
    asm volatile("griddepcontrol.wait;" ::: "memory");
}

__device__ __forceinline__ void mma16816(float* c, const uint32_t* a, const uint32_t* b){
    asm volatile("mma.sync.aligned.m16n8k16.row.col.f32.f16.f16.f32 "
        "{%0,%1,%2,%3}, {%4,%5,%6,%7}, {%8,%9}, {%0,%1,%2,%3};"
        : "+f"(c[0]),"+f"(c[1]),"+f"(c[2]),"+f"(c[3])
        : "r"(a[0]),"r"(a[1]),"r"(a[2]),"r"(a[3]), "r"(b[0]),"r"(b[1]));
}
__device__ __forceinline__ void ldsm4(uint32_t* r, uint32_t addr){
    asm volatile("ldmatrix.sync.aligned.m8n8.x4.shared.b16 {%0,%1,%2,%3}, [%4];"
        : "=r"(r[0]),"=r"(r[1]),"=r"(r[2]),"=r"(r[3]) : "r"(addr));
}
__device__ __forceinline__ uint32_t smem_u32(const void* p){
    return (uint32_t)__cvta_generic_to_shared(p);
}

// ---------------- fp16 2-pass split-K GEMM (A hi/lo exact, W single) ---------
// 128x128 tile, double-buffered smem, one sync per 32-k chunk. PDL: W chunk-0
// prefetch happens before griddepcontrol.wait; A reads after.
__global__ __launch_bounds__(256) void tgemm(
    const float* __restrict__ A, int lda,
    const hf* __restrict__ W,
    int NCg, int KPS)
{
    extern __shared__ __align__(16) char dyn[];

    const int t = threadIdx.x;
    const int w = t >> 5, lane = t & 31;
    const int g = lane >> 2, tig = lane & 3;
    const int ntile = blockIdx.x, z = blockIdx.y;
    const int n0 = ntile << 7;
    const int mrow = (w & 1) << 6;
    const int ncol = (w >> 1) << 5;
    const int lrow = t >> 1;
    const int lofs = (t & 1) << 4;

    const uint32_t smem0 = smem_u32(dyn);
    const uint32_t aoff = (uint32_t)(mrow + (lane & 15)) * 80u + (uint32_t)((lane >> 4) << 3) * 2u;
    const uint32_t boff = (uint32_t)(ncol + lane) * 80u;

    const float* aptr = A + (size_t)lrow * lda + lofs + (size_t)(z * KPS) * 32;
    const hf* wp = W + ((size_t)(ntile * NCg + z * KPS) * 128 + lrow) * 32 + lofs;

    float acc[4][4][4];
#pragma unroll
    for (int i=0;i<4;i++)
#pragma unroll
        for (int j=0;j<4;j++)
#pragma unroll
            for (int q2=0;q2<4;q2++) acc[i][j][q2]=0.f;

    float4 fa0, fa1, fa2, fa3;
    uint4 wr0, wr1;

#define SAH(bu) ((hf(*)[40])(dyn + (bu)*BUFB))
#define SAL(bu) ((hf(*)[40])(dyn + (bu)*BUFB + 10240))
#define SWW(bu) ((hf(*)[40])(dyn + (bu)*BUFB + 20480))

#define LOAD_W(ci) do { \
        wr0 = *(const uint4*)(wp + (size_t)(ci)*TILEB); \
        wr1 = *(const uint4*)(wp + (size_t)(ci)*TILEB + 8); \
    } while(0)

#define LOAD_A(ci) do { \
        const float* ap = aptr + (ci)*32; \
        fa0 = *(const float4*)(ap);    fa1 = *(const float4*)(ap+4); \
        fa2 = *(const float4*)(ap+8);  fa3 = *(const float4*)(ap+12); \
    } while(0)

#define STORE_SMEM(bu) do { \
        float fv[16] = {fa0.x,fa0.y,fa0.z,fa0.w, fa1.x,fa1.y,fa1.z,fa1.w, \
                        fa2.x,fa2.y,fa2.z,fa2.w, fa3.x,fa3.y,fa3.z,fa3.w}; \
        hf hv[16], lv[16]; \
        _Pragma("unroll") \
        for (int j=0;j<16;j++){ \
            hv[j] = __float2half(fv[j]); \
            lv[j] = __float2half(fv[j] - __half2float(hv[j])); \
        } \
        *(uint4*)&SAH(bu)[lrow][lofs]   = *(uint4*)&hv[0]; \
        *(uint4*)&SAH(bu)[lrow][lofs+8] = *(uint4*)&hv[8]; \
        *(uint4*)&SAL(bu)[lrow][lofs]   = *(uint4*)&lv[0]; \
        *(uint4*)&SAL(bu)[lrow][lofs+8] = *(uint4*)&lv[8]; \
        *(uint4*)&SWW(bu)[lrow][lofs]   = wr0; \
        *(uint4*)&SWW(bu)[lrow][lofs+8] = wr1; \
    } while(0)

    // PDL: prefetch static W while predecessor drains, then wait, then read A.
    LOAD_W(0);
    grid_wait();
    LOAD_A(0);
    STORE_SMEM(0);
    if (1 < KPS) { LOAD_W(1); LOAD_A(1); }
    __syncthreads();

    for (int ci = 0; ci < KPS; ci++) {
        const int cur = ci & 1;
        if (ci + 1 < KPS) {
            STORE_SMEM(cur ^ 1);
            if (ci + 2 < KPS) { LOAD_W(ci + 2); LOAD_A(ci + 2); }
        }
        const uint32_t bufb = smem0 + (uint32_t)cur * BUFB;
        const uint32_t aAh = bufb + aoff;
        const uint32_t aAl = aAh + 10240u;
        const uint32_t bW  = bufb + 20480u + boff;
#pragma unroll
        for (int k16 = 0; k16 < 32; k16 += 16) {
            uint32_t Ah[4][4], Al[4][4], B0[4], B1[4];
#pragma unroll
            for (int mt=0; mt<4; mt++){
                ldsm4(Ah[mt], aAh + (uint32_t)(mt*16*80) + (uint32_t)(k16*2));
                ldsm4(Al[mt], aAl + (uint32_t)(mt*16*80) + (uint32_t)(k16*2));
            }
            ldsm4(B0, bW + (uint32_t)(k16*2));
            ldsm4(B1, bW + (uint32_t)(k16*2) + 16u);
#pragma unroll
            for (int mt=0;mt<4;mt++)
#pragma unroll
                for (int nt=0;nt<4;nt++){
                    uint32_t b2[2] = {B0[nt], B1[nt]};
                    mma16816(acc[mt][nt], Ah[mt], b2);
                    mma16816(acc[mt][nt], Al[mt], b2);
                }
        }
        __syncthreads();
    }

#pragma unroll
    for (int mt=0; mt<4; mt++){
        int r0 = mrow + mt*16 + g;
#pragma unroll
        for (int nt=0; nt<4; nt++){
            int col = n0 + ncol + nt*8 + tig*2;
            float* p0 = g_part + ((size_t)(z*128 + r0))*4096 + col;
            float* p1 = g_part + ((size_t)(z*128 + r0 + 8))*4096 + col;
            *(float2*)p0 = make_float2(acc[mt][nt][0], acc[mt][nt][1]);
            *(float2*)p1 = make_float2(acc[mt][nt][2], acc[mt][nt][3]);
        }
    }
}

// ---------------- fused epilogues (PDL-aware) ----------------
__global__ void lstm_red(float* __restrict__ hst, int ldh, float* __restrict__ cst,
                         float* __restrict__ hout, int ldo,
                         const float* __restrict__ bi, const float* __restrict__ bh,
                         const int* __restrict__ kin, int step)
{
    int i = blockIdx.x*256 + threadIdx.x;            // BH
    int b = i >> 10, hh = i & 1023;
    grid_wait();
    float g[4];
#pragma unroll
    for (int gi=0; gi<4; gi++) {
        int col = (gi<<10) + hh;
        float s = bi[col] + bh[col];
#pragma unroll
        for (int zz=0; zz<KS_GATE; zz++)
            s += g_part[((size_t)(zz*128+b))*4096 + col];
        g[gi] = s;
    }
    float* hp = hst + (size_t)b*ldh + hh;
    float ho = *hp, co = cst[i];
    float cn = sigm(g[1])*co + sigm(g[0])*tanhf(g[2]);
    float hn = sigm(g[3])*tanhf(cn);
    hout[(size_t)b*ldo + hh] = hn;
    bool frozen = step >= kin[b];
    *hp    = frozen ? ho : hn;
    cst[i] = frozen ? co : cn;
}

__global__ void attn_core(const float* __restrict__ ctx, float* __restrict__ out,
                          const float* __restrict__ eps,
                          const float* __restrict__ mub, const float* __restrict__ sgb,
                          const int* __restrict__ kin, int step)
{
    __shared__ float sq[H];
    __shared__ float sal[SRC];
    int b = blockIdx.x, t = threadIdx.x;
    grid_wait();

    if (step >= 0) {                                 // fused zstep
        int zi = t;
        float m = mub[zi], s = sgb[zi];
#pragma unroll
        for (int zz=0; zz<KS_GEN; zz++) {
            const float* p = g_part + ((size_t)(zz*128+b))*4096;
            m += p[zi];
            s += p[256+zi];
        }
        float zval = m + expf(s) * eps[((size_t)step*B + b)*Z + zi];
        g_x0[(size_t)b*X0LD + zi] = zval;
        bool valid = step < kin[b];
        size_t o = ((size_t)b*KMAX + step)*Z + zi;
        out[o]          = valid ? zval : 0.f;
        out[OUT_MU + o] = valid ? m : 0.f;
        out[OUT_SG + o] = valid ? s : 0.f;
    }

    for (int i=t; i<H; i+=256) {                     // qw reduce (cols 512..1535)
        float s = 0.f;
#pragma unroll
        for (int zz=0; zz<KS_GEN; zz++)
            s += g_part[((size_t)(zz*128+b))*4096 + 512 + i];
        sq[i] = s;
    }
    __syncthreads();
    int warp = t>>5, lane = t&31;
#pragma unroll
    for (int s8=0; s8<8; s8++) {
        int s = warp*8 + s8;
        const float* cr = ctx + ((size_t)b*SRC + s)*H;
        float a = 0.f;
        for (int k2=lane; k2<H; k2+=32) a += cr[k2]*sq[k2];
#pragma unroll
        for (int o=16;o>0;o>>=1) a += __shfl_xor_sync(0xffffffffu, a, o);
        if (lane==0) sal[s] = a;
    }
    __syncthreads();
    if (warp==0) {
        float v0 = sal[lane], v1 = sal[lane+32];
        float mx = fmaxf(v0,v1);
#pragma unroll
        for (int o=16;o>0;o>>=1) mx = fmaxf(mx, __shfl_xor_sync(0xffffffffu,mx,o));
        float e0=expf(v0-mx), e1=expf(v1-mx);
        float sm=e0+e1;
#pragma unroll
        for (int o=16;o>0;o>>=1) sm += __shfl_xor_sync(0xffffffffu,sm,o);
        float inv=1.f/sm;
        sal[lane]=e0*inv; sal[lane+32]=e1*inv;
    }
    __syncthreads();
    for (int hh=t; hh<H; hh+=256) {
        float a=0.f;
#pragma unroll 8
        for (int s=0;s<SRC;s++) a += sal[s]*ctx[((size_t)b*SRC+s)*H + hh];
        g_xa[(size_t)b*X1LD + hh] = a;
    }
}

__global__ void attnout_red()
{
    int i = blockIdx.x*256 + threadIdx.x;            // BH
    int b = i>>10, hh = i&1023;
    grid_wait();
    float s = 0.f;
#pragma unroll
    for (int zz=0; zz<KS_OUT; zz++)
        s += g_part[((size_t)(zz*128+b))*4096 + hh];
    g_x0[(size_t)b*X0LD + 257 + hh] = tanhf(s);
}

// ---------------- weight prep: fp32 -> fp16 blocked (128x32) ----------------
__device__ __forceinline__ void put_tile(hf* dst, int NCg, int n, int k, float v){
    int ntile = n >> 7, nin = n & 127, chunk = k >> 5, kin = k & 31;
    size_t d = ((size_t)(ntile * NCg + chunk) * 128 + nin) * 32 + kin;
    dst[d] = __float2half(v);
}
__global__ void prep0(const float* __restrict__ Wih, const float* __restrict__ Whh){
    int i = blockIdx.x*256 + threadIdx.x;
    int n = i / X0LD, k = i - n*X0LD;
    float v;
    if (k < 1281)       v = Wih[(size_t)n*1281 + k];
    else if (k < H0OFF) v = 0.f;
    else                v = Whh[(size_t)n*1024 + (k-H0OFF)];
    put_tile(g_w0, NC0, n, k, v);
}
__global__ void prep1(const float* __restrict__ Wih, const float* __restrict__ Whh){
    int i = blockIdx.x*256 + threadIdx.x;
    int n = i >> 11, k = i & 2047;
    float v = (k < 1024) ? Wih[(size_t)n*1024 + k] : Whh[(size_t)n*1024 + (k-1024)];
    put_tile(g_w1, NC1, n, k, v);
}
__global__ void prepg(const float* __restrict__ muW, const float* __restrict__ sgW,
                      const float* __restrict__ aWin){
    int i = blockIdx.x*256 + threadIdx.x;
    int n = i >> 10, k = i & 1023;
    float v;
    if (n < 256)      v = muW[(size_t)n*1024 + k];
    else if (n < 512) v = sgW[(size_t)(n-256)*1024 + k];
    else              v = aWin[(size_t)(n-512)*1024 + k];
    put_tile(g_wg, NCG, n, k, v);
}
__global__ void prepo(const float* __restrict__ aWout){
    int i = blockIdx.x*256 + threadIdx.x;
    int n = i >> 11, k = i & 2047;
    put_tile(g_wo, NCO, n, k, aWout[(size_t)n*2048 + k]);
}

// ---------------- init / final ----------------
__global__ void init_a(const float* __restrict__ z0, const int* __restrict__ kin,
                       const float* __restrict__ h0){
    int i = blockIdx.x*256 + threadIdx.x;
    int b = i / X0LD, c = i - b*X0LD;
    float v = 0.f;
    if (c < 256)         v = z0[(b<<8) + c];
    else if (c == 256)   v = (float)kin[b];
    else if (c >= H0OFF) v = h0[(b<<10) + (c-H0OFF)];
    g_x0[i] = v;
}
__global__ void init_b(const float* __restrict__ h0, const float* __restrict__ c0){
    int i = blockIdx.x*256 + threadIdx.x;
    int b = i >> 11, c = i & 2047;
    g_x1[i] = (c < 1024) ? 0.f : h0[BH + (b<<10) + (c-1024)];
    g_xa[i] = (c < 1024) ? 0.f : c0[BH + (b<<10) + (c-1024)];
    g_c[i]  = c0[i];
}
__global__ void final_copy(float* __restrict__ out){
    int i = blockIdx.x*256 + threadIdx.x;
    int b = i>>10, hh = i&1023;
    grid_wait();
    out[OUT_H + i]      = g_x0[(size_t)b*X0LD + H0OFF + hh];
    out[OUT_H + BH + i] = g_x1[(size_t)b*X1LD + 1024 + hh];
    out[OUT_C + i]      = g_c[i];
    out[OUT_C + BH + i] = g_c[BH + i];
}

// ---------------- orchestration ----------------
#define PDL_LAUNCH(kern, grid, nthr, smem, ...) do { \
    cudaLaunchConfig_t _cfg = {}; \
    _cfg.gridDim = grid; _cfg.blockDim = dim3(nthr,1,1); \
    _cfg.dynamicSmemBytes = smem; _cfg.stream = 0; \
    cudaLaunchAttribute _at[1]; \
    _at[0].id = cudaLaunchAttributeProgrammaticStreamSerialization; \
    _at[0].val.programmaticStreamSerializationAllowed = 1; \
    _cfg.attrs = _at; _cfg.numAttrs = 1; \
    cudaLaunchKernelEx(&_cfg, kern, ##__VA_ARGS__); \
} while(0)

extern "C" void kernel_launch(void* const* d_in, const int* in_sizes, int n_in,
                              void* d_out, int out_size) {
    const float* h0    = (const float*)d_in[0];
    const float* c0    = (const float*)d_in[1];
    const float* ctx   = (const float*)d_in[2];
    const float* z0    = (const float*)d_in[3];
    const int*   kin   = (const int*)  d_in[4];
    const float* eps   = (const float*)d_in[5];
    const float* W_ih0 = (const float*)d_in[6];
    const float* W_hh0 = (const float*)d_in[7];
    const float* b_ih0 = (const float*)d_in[8];
    const float* b_hh0 = (const float*)d_in[9];
    const float* W_ih1 = (const float*)d_in[10];
    const float* W_hh1 = (const float*)d_in[11];
    const float* b_ih1 = (const float*)d_in[12];
    const float* b_hh1 = (const float*)d_in[13];
    const float* aWin  = (const float*)d_in[14];
    const float* aWout = (const float*)d_in[15];
    const float* mu_W  = (const float*)d_in[16];
    const float* mu_b  = (const float*)d_in[17];
    const float* sg_W  = (const float*)d_in[18];
    const float* sg_b  = (const float*)d_in[19];
    float* out = (float*)d_out;

    static int s_attr_set = 0;
    if (!s_attr_set) {
        cudaFuncSetAttribute(tgemm, cudaFuncAttributeMaxDynamicSharedMemorySize, DSMEM);
        s_attr_set = 1;
    }

    float *p_x0, *p_x1, *p_xa, *p_c;
    hf *w0, *w1, *wg, *wo;
    cudaGetSymbolAddress((void**)&p_x0, g_x0);
    cudaGetSymbolAddress((void**)&p_x1, g_x1);
    cudaGetSymbolAddress((void**)&p_xa, g_xa);
    cudaGetSymbolAddress((void**)&p_c,  g_c);
    cudaGetSymbolAddress((void**)&w0, g_w0);
    cudaGetSymbolAddress((void**)&w1, g_w1);
    cudaGetSymbolAddress((void**)&wg, g_wg);
    cudaGetSymbolAddress((void**)&wo, g_wo);

    prep0<<<(G4*X0LD)/256, 256>>>(W_ih0, W_hh0);
    prep1<<<(G4*X1LD)/256, 256>>>(W_ih1, W_hh1);
    prepg<<<(1536*H)/256, 256>>>(mu_W, sg_W, aWin);
    prepo<<<(H*2048)/256, 256>>>(aWout);
    init_a<<<(B*X0LD)/256, 256>>>(z0, kin, h0);
    init_b<<<(B*X1LD)/256, 256>>>(h0, c0);

    // attn0: q = c0[-1] (step=-1 skips fused zstep)
    PDL_LAUNCH(tgemm, dim3(12, KS_GEN), 256, DSMEM, c0 + BH, (int)H, (const hf*)wg, (int)NCG, (int)(NCG/KS_GEN));
    PDL_LAUNCH(attn_core, dim3(B), 256, 0, ctx, out, eps, mu_b, sg_b, kin, -1);
    PDL_LAUNCH(tgemm, dim3(8, KS_OUT), 256, DSMEM, (const float*)p_xa, (int)X1LD, (const hf*)wo, (int)NCO, (int)(NCO/KS_OUT));
    PDL_LAUNCH(attnout_red, dim3(BH/256), 256, 0);

    for (int step = 0; step < KMAX; step++) {
        PDL_LAUNCH(tgemm, dim3(32, KS_GATE), 256, DSMEM, (const float*)p_x0, (int)X0LD, (const hf*)w0, (int)NC0, (int)(NC0/KS_GATE));
        PDL_LAUNCH(lstm_red, dim3(BH/256), 256, 0, p_x0 + H0OFF, (int)X0LD, p_c, p_x1, (int)X1LD, b_ih0, b_hh0, kin, step);
        PDL_LAUNCH(tgemm, dim3(32, KS_GATE), 256, DSMEM, (const float*)p_x1, (int)X1LD, (const hf*)w1, (int)NC1, (int)(NC1/KS_GATE));
        PDL_LAUNCH(lstm_red, dim3(BH/256), 256, 0, p_x1 + 1024, (int)X1LD, p_c + BH, p_xa + 1024, (int)X1LD, b_ih1, b_hh1, kin, step);
        PDL_LAUNCH(tgemm, dim3(12, KS_GEN), 256, DSMEM, (const float*)(p_xa + 1024), (int)X1LD, (const hf*)wg, (int)NCG, (int)(NCG/KS_GEN));
        PDL_LAUNCH(attn_core, dim3(B), 256, 0, ctx, out, eps, mu_b, sg_b, kin, step);
        PDL_LAUNCH(tgemm, dim3(8, KS_OUT), 256, DSMEM, (const float*)p_xa, (int)X1LD, (const hf*)wo, (int)NCO, (int)(NCO/KS_OUT));
        PDL_LAUNCH(attnout_red, dim3(BH/256), 256, 0);
    }

    PDL_LAUNCH(final_copy, dim3(BH/256), 256, 0, out);
    (void)in_sizes; (void)n_in; (void)out_size;
}

// round 16
// speedup vs baseline: 1.3444x; 1.0249x over previous
#include <cuda_runtime.h>
#include <cuda_fp16.h>
#include <math.h>
#include <stdint.h>

#define B     128
#define H     1024
#define Z     256
#define SRC   64
#define KMAX  48
#define BH    (B*H)
#define X0LD  2432          // [z(256) | k(1) | attn(1024) | pad(127) | h0(1024)]
#define H0OFF 1408
#define X1LD  2048          // [h0n | h1]
#define G4    4096
#define KS_GATE 4
#define KS_GEN  8
#define KS_OUT  16
#define NC0   76            // X0LD/32
#define NC1   64
#define NCG   32
#define NCO   64

// out layout: z[B,K,Z] | mu | sigma | h_f[2,B,H] | c_f[2,B,H]
#define OUT_MU 1572864
#define OUT_SG 3145728
#define OUT_H  4718592
#define OUT_C  4980736

#define TILEB 4096          // fp16 elements per 128x32 W block
#define BUFB  30720         // bytes per smem buffer set (Ah,Al,W)
#define DSMEM 61440

typedef __half hf;

// ---------------- device scratch (batch-permuted space) ----------------
__device__ __align__(16) float g_x0[B*X0LD];
__device__ __align__(16) float g_x1[B*X1LD];
__device__ __align__(16) float g_xa[B*X1LD];        // [weighted | q]
__device__ __align__(16) float g_c[2*BH];
__device__ __align__(16) float g_part[16*B*G4];
__device__ __align__(16) hf g_w0[G4*X0LD];
__device__ __align__(16) hf g_w1[G4*X1LD];
__device__ __align__(16) hf g_wg[1536*H];
__device__ __align__(16) hf g_wo[H*2048];
__device__ int g_perm[B];       // permuted row -> original batch
__device__ int g_nact[KMAX];    // #{k > s}

__device__ __forceinline__ float sigm(float x){ return 1.f/(1.f+expf(-x)); }
__device__ __forceinline__ void grid_wait(){
    asm volatile("griddepcontrol.wait;" ::: "memory");
}

__device__ __forceinline__ void mma16816(float* c, const uint32_t* a, const uint32_t* b){
    asm volatile("mma.sync.aligned.m16n8k16.row.col.f32.f16.f16.f32 "
        "{%0,%1,%2,%3}, {%4,%5,%6,%7}, {%8,%9}, {%0,%1,%2,%3};"
        : "+f"(c[0]),"+f"(c[1]),"+f"(c[2]),"+f"(c[3])
        : "r"(a[0]),"r"(a[1]),"r"(a[2]),"r"(a[3]), "r"(b[0]),"r"(b[1]));
}
__device__ __forceinline__ void ldsm4(uint32_t* r, uint32_t addr){
    asm volatile("ldmatrix.sync.aligned.m8n8.x4.shared.b16 {%0,%1,%2,%3}, [%4];"
        : "=r"(r[0]),"=r"(r[1]),"=r"(r[2]),"=r"(r[3]) : "r"(addr));
}
__device__ __forceinline__ uint32_t smem_u32(const void* p){
    return (uint32_t)__cvta_generic_to_shared(p);
}

// ---------------- batch sort by k descending (stable) + nact table -----------
__global__ void sortk(const int* __restrict__ kin){
    if (threadIdx.x == 0){
        int counts[49];
        for (int i=0;i<49;i++) counts[i]=0;
        for (int b=0;b<B;b++) counts[kin[b]]++;
        for (int s=0;s<KMAX;s++){
            int c=0;
            for (int kk=s+1;kk<=48;kk++) c+=counts[kk];
            g_nact[s]=c;
        }
        int start[49];
        for (int kk=1;kk<=48;kk++){
            int c=0;
            for (int k2=kk+1;k2<=48;k2++) c+=counts[k2];
            start[kk]=c;
        }
        for (int b=0;b<B;b++)
            g_perm[start[kin[b]]++] = b;
    }
}

// ---------------- fp16 2-pass split-K GEMM with active-row skipping ----------
__global__ __launch_bounds__(256) void tgemm(
    const float* __restrict__ A, int lda,
    const hf* __restrict__ W,
    int NCg, int KPS, int stepidx)
{
    extern __shared__ __align__(16) char dyn[];

    const int t = threadIdx.x;
    const int w = t >> 5, lane = t & 31;
    const int g = lane >> 2, tig = lane & 3;
    const int ntile = blockIdx.x, z = blockIdx.y;
    const int n0 = ntile << 7;
    const int mrow = (w & 1) << 6;
    const int ncol = (w >> 1) << 5;
    const int lrow = t >> 1;
    const int lofs = (t & 1) << 4;

    const int nact = (stepidx < 0) ? B : g_nact[stepidx];
    const bool wact = (mrow < nact);
    const int mlim = nact - mrow;
    const bool arow_on = (lrow < nact);

    const uint32_t smem0 = smem_u32(dyn);
    const uint32_t aoff = (uint32_t)(mrow + (lane & 15)) * 80u + (uint32_t)((lane >> 4) << 3) * 2u;
    const uint32_t boff = (uint32_t)(ncol + lane) * 80u;

    const float* aptr = A + (size_t)lrow * lda + lofs + (size_t)(z * KPS) * 32;
    const hf* wp = W + ((size_t)(ntile * NCg + z * KPS) * 128 + lrow) * 32 + lofs;

    float acc[4][4][4];
#pragma unroll
    for (int i=0;i<4;i++)
#pragma unroll
        for (int j=0;j<4;j++)
#pragma unroll
            for (int q2=0;q2<4;q2++) acc[i][j][q2]=0.f;

    float4 fa0=make_float4(0,0,0,0), fa1=fa0, fa2=fa0, fa3=fa0;
    uint4 wr0, wr1;

#define SAH(bu) ((hf(*)[40])(dyn + (bu)*BUFB))
#define SAL(bu) ((hf(*)[40])(dyn + (bu)*BUFB + 10240))
#define SWW(bu) ((hf(*)[40])(dyn + (bu)*BUFB + 20480))

#define LOAD_W(ci) do { \
        wr0 = *(const uint4*)(wp + (size_t)(ci)*TILEB); \
        wr1 = *(const uint4*)(wp + (size_t)(ci)*TILEB + 8); \
    } while(0)

#define LOAD_A(ci) do { if (arow_on) { \
        const float* ap = aptr + (ci)*32; \
        fa0 = *(const float4*)(ap);    fa1 = *(const float4*)(ap+4); \
        fa2 = *(const float4*)(ap+8);  fa3 = *(const float4*)(ap+12); \
    } } while(0)

#define STORE_SMEM(bu) do { \
        float fv[16] = {fa0.x,fa0.y,fa0.z,fa0.w, fa1.x,fa1.y,fa1.z,fa1.w, \
                        fa2.x,fa2.y,fa2.z,fa2.w, fa3.x,fa3.y,fa3.z,fa3.w}; \
        hf hv[16], lv[16]; \
        _Pragma("unroll") \
        for (int j=0;j<16;j++){ \
            hv[j] = __float2half(fv[j]); \
            lv[j] = __float2half(fv[j] - __half2float(hv[j])); \
        } \
        *(uint4*)&SAH(bu)[lrow][lofs]   = *(uint4*)&hv[0]; \
        *(uint4*)&SAH(bu)[lrow][lofs+8] = *(uint4*)&hv[8]; \
        *(uint4*)&SAL(bu)[lrow][lofs]   = *(uint4*)&lv[0]; \
        *(uint4*)&SAL(bu)[lrow][lofs+8] = *(uint4*)&lv[8]; \
        *(uint4*)&SWW(bu)[lrow][lofs]   = wr0; \
        *(uint4*)&SWW(bu)[lrow][lofs+8] = wr1; \
    } while(0)

    // PDL: prefetch static W while predecessor drains, then wait, then read A.
    LOAD_W(0);
    grid_wait();
    LOAD_A(0);
    STORE_SMEM(0);
    if (1 < KPS) { LOAD_W(1); LOAD_A(1); }
    __syncthreads();

    for (int ci = 0; ci < KPS; ci++) {
        const int cur = ci & 1;
        if (ci + 1 < KPS) {
            STORE_SMEM(cur ^ 1);
            if (ci + 2 < KPS) { LOAD_W(ci + 2); LOAD_A(ci + 2); }
        }
        if (wact) {
            const uint32_t bufb = smem0 + (uint32_t)cur * BUFB;
            const uint32_t aAh = bufb + aoff;
            const uint32_t aAl = aAh + 10240u;
            const uint32_t bW  = bufb + 20480u + boff;
#pragma unroll
            for (int k16 = 0; k16 < 32; k16 += 16) {
                uint32_t Ah[4][4], Al[4][4], B0[4], B1[4];
#pragma unroll
                for (int mt=0; mt<4; mt++){
                    if (mt*16 < mlim) {
                        ldsm4(Ah[mt], aAh + (uint32_t)(mt*16*80) + (uint32_t)(k16*2));
                        ldsm4(Al[mt], aAl + (uint32_t)(mt*16*80) + (uint32_t)(k16*2));
                    }
                }
                ldsm4(B0, bW + (uint32_t)(k16*2));
                ldsm4(B1, bW + (uint32_t)(k16*2) + 16u);
#pragma unroll
                for (int mt=0;mt<4;mt++){
                    if (mt*16 < mlim) {
#pragma unroll
                        for (int nt=0;nt<4;nt++){
                            uint32_t b2[2] = {B0[nt], B1[nt]};
                            mma16816(acc[mt][nt], Ah[mt], b2);
                            mma16816(acc[mt][nt], Al[mt], b2);
                        }
                    }
                }
            }
        }
        __syncthreads();
    }

#pragma unroll
    for (int mt=0; mt<4; mt++){
        if (mrow + mt*16 >= nact) continue;
        int r0 = mrow + mt*16 + g;
#pragma unroll
        for (int nt=0; nt<4; nt++){
            int col = n0 + ncol + nt*8 + tig*2;
            float* p0 = g_part + ((size_t)(z*128 + r0))*4096 + col;
            float* p1 = g_part + ((size_t)(z*128 + r0 + 8))*4096 + col;
            *(float2*)p0 = make_float2(acc[mt][nt][0], acc[mt][nt][1]);
            *(float2*)p1 = make_float2(acc[mt][nt][2], acc[mt][nt][3]);
        }
    }
}

// ---------------- fused epilogues (permuted space, active-prefix skip) -------
__global__ void lstm_red(float* __restrict__ hst, int ldh, float* __restrict__ cst,
                         float* __restrict__ hout, int ldo,
                         const float* __restrict__ bi, const float* __restrict__ bh,
                         const int* __restrict__ kin, int step)
{
    int i = blockIdx.x*256 + threadIdx.x;            // BH (permuted rows)
    int b = i >> 10, hh = i & 1023;
    grid_wait();
    if (b >= g_nact[step]) return;                   // dead prefix-complement
    int borig = g_perm[b];
    float g[4];
#pragma unroll
    for (int gi=0; gi<4; gi++) {
        int col = (gi<<10) + hh;
        float s = bi[col] + bh[col];
#pragma unroll
        for (int zz=0; zz<KS_GATE; zz++)
            s += g_part[((size_t)(zz*128+b))*4096 + col];
        g[gi] = s;
    }
    float* hp = hst + (size_t)b*ldh + hh;
    float ho = *hp, co = cst[i];
    float cn = sigm(g[1])*co + sigm(g[0])*tanhf(g[2]);
    float hn = sigm(g[3])*tanhf(cn);
    hout[(size_t)b*ldo + hh] = hn;
    bool frozen = step >= kin[borig];
    *hp    = frozen ? ho : hn;
    cst[i] = frozen ? co : cn;
}

__global__ void attn_core(const float* __restrict__ ctx, float* __restrict__ out,
                          const float* __restrict__ eps,
                          const float* __restrict__ mub, const float* __restrict__ sgb,
                          const int* __restrict__ kin, int step)
{
    __shared__ float sq[H];
    __shared__ float sal[SRC];
    int bs = blockIdx.x, t = threadIdx.x;
    grid_wait();
    int borig = g_perm[bs];

    if (step >= 0) {                                 // fused zstep (always runs: masked zeros)
        int zi = t;
        float m = mub[zi], s = sgb[zi];
#pragma unroll
        for (int zz=0; zz<KS_GEN; zz++) {
            const float* p = g_part + ((size_t)(zz*128+bs))*4096;
            m += p[zi];
            s += p[256+zi];
        }
        float zval = m + expf(s) * eps[((size_t)step*B + borig)*Z + zi];
        g_x0[(size_t)bs*X0LD + zi] = zval;
        bool valid = step < kin[borig];
        size_t o = ((size_t)borig*KMAX + step)*Z + zi;
        out[o]          = valid ? zval : 0.f;
        out[OUT_MU + o] = valid ? m : 0.f;
        out[OUT_SG + o] = valid ? s : 0.f;
    }
    if (step >= 0 && bs >= g_nact[step]) return;     // skip heavy ctx work for dead batches

    for (int i=t; i<H; i+=256) {                     // qw reduce (cols 512..1535)
        float s = 0.f;
#pragma unroll
        for (int zz=0; zz<KS_GEN; zz++)
            s += g_part[((size_t)(zz*128+bs))*4096 + 512 + i];
        sq[i] = s;
    }
    __syncthreads();
    int warp = t>>5, lane = t&31;
#pragma unroll
    for (int s8=0; s8<8; s8++) {
        int s = warp*8 + s8;
        const float* cr = ctx + ((size_t)borig*SRC + s)*H;
        float a = 0.f;
        for (int k2=lane; k2<H; k2+=32) a += cr[k2]*sq[k2];
#pragma unroll
        for (int o=16;o>0;o>>=1) a += __shfl_xor_sync(0xffffffffu, a, o);
        if (lane==0) sal[s] = a;
    }
    __syncthreads();
    if (warp==0) {
        float v0 = sal[lane], v1 = sal[lane+32];
        float mx = fmaxf(v0,v1);
#pragma unroll
        for (int o=16;o>0;o>>=1) mx = fmaxf(mx, __shfl_xor_sync(0xffffffffu,mx,o));
        float e0=expf(v0-mx), e1=expf(v1-mx);
        float sm=e0+e1;
#pragma unroll
        for (int o=16;o>0;o>>=1) sm += __shfl_xor_sync(0xffffffffu,sm,o);
        float inv=1.f/sm;
        sal[lane]=e0*inv; sal[lane+32]=e1*inv;
    }
    __syncthreads();
    for (int hh=t; hh<H; hh+=256) {
        float a=0.f;
#pragma unroll 8
        for (int s=0;s<SRC;s++) a += sal[s]*ctx[((size_t)borig*SRC+s)*H + hh];
        g_xa[(size_t)bs*X1LD + hh] = a;
    }
}

__global__ void attnout_red(int step)
{
    int i = blockIdx.x*256 + threadIdx.x;            // BH (permuted rows)
    int b = i>>10, hh = i&1023;
    grid_wait();
    if (step >= 0 && b >= g_nact[step]) return;
    float s = 0.f;
#pragma unroll
    for (int zz=0; zz<KS_OUT; zz++)
        s += g_part[((size_t)(zz*128+b))*4096 + hh];
    g_x0[(size_t)b*X0LD + 257 + hh] = tanhf(s);
}

// ---------------- weight prep: fp32 -> fp16 blocked (128x32) ----------------
__device__ __forceinline__ void put_tile(hf* dst, int NCg, int n, int k, float v){
    int ntile = n >> 7, nin = n & 127, chunk = k >> 5, kin = k & 31;
    size_t d = ((size_t)(ntile * NCg + chunk) * 128 + nin) * 32 + kin;
    dst[d] = __float2half(v);
}
__global__ void prep0(const float* __restrict__ Wih, const float* __restrict__ Whh){
    int i = blockIdx.x*256 + threadIdx.x;
    int n = i / X0LD, k = i - n*X0LD;
    float v;
    if (k < 1281)       v = Wih[(size_t)n*1281 + k];
    else if (k < H0OFF) v = 0.f;
    else                v = Whh[(size_t)n*1024 + (k-H0OFF)];
    put_tile(g_w0, NC0, n, k, v);
}
__global__ void prep1(const float* __restrict__ Wih, const float* __restrict__ Whh){
    int i = blockIdx.x*256 + threadIdx.x;
    int n = i >> 11, k = i & 2047;
    float v = (k < 1024) ? Wih[(size_t)n*1024 + k] : Whh[(size_t)n*1024 + (k-1024)];
    put_tile(g_w1, NC1, n, k, v);
}
__global__ void prepg(const float* __restrict__ muW, const float* __restrict__ sgW,
                      const float* __restrict__ aWin){
    int i = blockIdx.x*256 + threadIdx.x;
    int n = i >> 10, k = i & 1023;
    float v;
    if (n < 256)      v = muW[(size_t)n*1024 + k];
    else if (n < 512) v = sgW[(size_t)(n-256)*1024 + k];
    else              v = aWin[(size_t)(n-512)*1024 + k];
    put_tile(g_wg, NCG, n, k, v);
}
__global__ void prepo(const float* __restrict__ aWout){
    int i = blockIdx.x*256 + threadIdx.x;
    int n = i >> 11, k = i & 2047;
    put_tile(g_wo, NCO, n, k, aWout[(size_t)n*2048 + k]);
}

// ---------------- init / final (apply permutation) ----------------
__global__ void init_a(const float* __restrict__ z0, const int* __restrict__ kin,
                       const float* __restrict__ h0){
    int i = blockIdx.x*256 + threadIdx.x;
    int b = i / X0LD, c = i - b*X0LD;
    int borig = g_perm[b];
    float v = 0.f;
    if (c < 256)         v = z0[(borig<<8) + c];
    else if (c == 256)   v = (float)kin[borig];
    else if (c >= H0OFF) v = h0[(borig<<10) + (c-H0OFF)];
    g_x0[i] = v;
}
__global__ void init_b(const float* __restrict__ h0, const float* __restrict__ c0){
    int i = blockIdx.x*256 + threadIdx.x;
    int b = i >> 11, c = i & 2047;
    int borig = g_perm[b];
    g_x1[i] = (c < 1024) ? 0.f : h0[BH + (borig<<10) + (c-1024)];
    g_xa[i] = (c < 1024) ? 0.f : c0[BH + (borig<<10) + (c-1024)];
    g_c[i]  = c0[(borig<<10) + (c & 1023) + ((c < 1024) ? 0 : 0)];
    // layer: g_c layout is [layer0 rows | layer1 rows] over permuted b:
    // i < BH -> layer0 row b2=i>>10 ; i >= BH handled below
}
__global__ void init_c(const float* __restrict__ c0){
    int i = blockIdx.x*256 + threadIdx.x;            // 2*BH
    int layer = i >= BH;
    int r = (i - (layer ? BH : 0)) >> 10, hh = i & 1023;
    int borig = g_perm[r];
    g_c[i] = c0[(layer ? BH : 0) + (borig<<10) + hh];
}
__global__ void final_copy(float* __restrict__ out){
    int i = blockIdx.x*256 + threadIdx.x;            // BH
    int b = i>>10, hh = i&1023;
    grid_wait();
    int borig = g_perm[b];
    out[OUT_H + (borig<<10) + hh]      = g_x0[(size_t)b*X0LD + H0OFF + hh];
    out[OUT_H + BH + (borig<<10) + hh] = g_x1[(size_t)b*X1LD + 1024 + hh];
    out[OUT_C + (borig<<10) + hh]      = g_c[i];
    out[OUT_C + BH + (borig<<10) + hh] = g_c[BH + i];
}

// ---------------- orchestration ----------------
#define PDL_LAUNCH(kern, grid, nthr, smem, ...) do { \
    cudaLaunchConfig_t _cfg = {}; \
    _cfg.gridDim = grid; _cfg.blockDim = dim3(nthr,1,1); \
    _cfg.dynamicSmemBytes = smem; _cfg.stream = 0; \
    cudaLaunchAttribute _at[1]; \
    _at[0].id = cudaLaunchAttributeProgrammaticStreamSerialization; \
    _at[0].val.programmaticStreamSerializationAllowed = 1; \
    _cfg.attrs = _at; _cfg.numAttrs = 1; \
    cudaLaunchKernelEx(&_cfg, kern, ##__VA_ARGS__); \
} while(0)

extern "C" void kernel_launch(void* const* d_in, const int* in_sizes, int n_in,
                              void* d_out, int out_size) {
    const float* h0    = (const float*)d_in[0];
    const float* c0    = (const float*)d_in[1];
    const float* ctx   = (const float*)d_in[2];
    const float* z0    = (const float*)d_in[3];
    const int*   kin   = (const int*)  d_in[4];
    const float* eps   = (const float*)d_in[5];
    const float* W_ih0 = (const float*)d_in[6];
    const float* W_hh0 = (const float*)d_in[7];
    const float* b_ih0 = (const float*)d_in[8];
    const float* b_hh0 = (const float*)d_in[9];
    const float* W_ih1 = (const float*)d_in[10];
    const float* W_hh1 = (const float*)d_in[11];
    const float* b_ih1 = (const float*)d_in[12];
    const float* b_hh1 = (const float*)d_in[13];
    const float* aWin  = (const float*)d_in[14];
    const float* aWout = (const float*)d_in[15];
    const float* mu_W  = (const float*)d_in[16];
    const float* mu_b  = (const float*)d_in[17];
    const float* sg_W  = (const float*)d_in[18];
    const float* sg_b  = (const float*)d_in[19];
    float* out = (float*)d_out;

    static int s_attr_set = 0;
    if (!s_attr_set) {
        cudaFuncSetAttribute(tgemm, cudaFuncAttributeMaxDynamicSharedMemorySize, DSMEM);
        s_attr_set = 1;
    }

    float *p_x0, *p_x1, *p_xa, *p_c;
    hf *w0, *w1, *wg, *wo;
    cudaGetSymbolAddress((void**)&p_x0, g_x0);
    cudaGetSymbolAddress((void**)&p_x1, g_x1);
    cudaGetSymbolAddress((void**)&p_xa, g_xa);
    cudaGetSymbolAddress((void**)&p_c,  g_c);
    cudaGetSymbolAddress((void**)&w0, g_w0);
    cudaGetSymbolAddress((void**)&w1, g_w1);
    cudaGetSymbolAddress((void**)&wg, g_wg);
    cudaGetSymbolAddress((void**)&wo, g_wo);

    sortk<<<1, 32>>>(kin);
    prep0<<<(G4*X0LD)/256, 256>>>(W_ih0, W_hh0);
    prep1<<<(G4*X1LD)/256, 256>>>(W_ih1, W_hh1);
    prepg<<<(1536*H)/256, 256>>>(mu_W, sg_W, aWin);
    prepo<<<(H*2048)/256, 256>>>(aWout);
    init_a<<<(B*X0LD)/256, 256>>>(z0, kin, h0);
    init_b<<<(B*X1LD)/256, 256>>>(h0, c0);
    init_c<<<(2*BH)/256, 256>>>(c0);

    // attn0: q = c0[-1] (permuted copy lives in g_xa right half)
    PDL_LAUNCH(tgemm, dim3(12, KS_GEN), 256, DSMEM, (const float*)(p_xa + 1024), (int)X1LD, (const hf*)wg, (int)NCG, (int)(NCG/KS_GEN), -1);
    PDL_LAUNCH(attn_core, dim3(B), 256, 0, ctx, out, eps, mu_b, sg_b, kin, -1);
    PDL_LAUNCH(tgemm, dim3(8, KS_OUT), 256, DSMEM, (const float*)p_xa, (int)X1LD, (const hf*)wo, (int)NCO, (int)(NCO/KS_OUT), -1);
    PDL_LAUNCH(attnout_red, dim3(BH/256), 256, 0, -1);

    for (int step = 0; step < KMAX; step++) {
        PDL_LAUNCH(tgemm, dim3(32, KS_GATE), 256, DSMEM, (const float*)p_x0, (int)X0LD, (const hf*)w0, (int)NC0, (int)(NC0/KS_GATE), step);
        PDL_LAUNCH(lstm_red, dim3(BH/256), 256, 0, p_x0 + H0OFF, (int)X0LD, p_c, p_x1, (int)X1LD, b_ih0, b_hh0, kin, step);
        PDL_LAUNCH(tgemm, dim3(32, KS_GATE), 256, DSMEM, (const float*)p_x1, (int)X1LD, (const hf*)w1, (int)NC1, (int)(NC1/KS_GATE), step);
        PDL_LAUNCH(lstm_red, dim3(BH/256), 256, 0, p_x1 + 1024, (int)X1LD, p_c + BH, p_xa + 1024, (int)X1LD, b_ih1, b_hh1, kin, step);
        PDL_LAUNCH(tgemm, dim3(12, KS_GEN), 256, DSMEM, (const float*)(p_xa + 1024), (int)X1LD, (const hf*)wg, (int)NCG, (int)(NCG/KS_GEN), step);
        PDL_LAUNCH(attn_core, dim3(B), 256, 0, ctx, out, eps, mu_b, sg_b, kin, step);
        PDL_LAUNCH(tgemm, dim3(8, KS_OUT), 256, DSMEM, (const float*)p_xa, (int)X1LD, (const hf*)wo, (int)NCO, (int)(NCO/KS_OUT), step);
        PDL_LAUNCH(attnout_red, dim3(BH/256), 256, 0, step);
    }

    PDL_LAUNCH(final_copy, dim3(BH/256), 256, 0, out);
    (void)in_sizes; (void)n_in; (void)out_size;
}